// round 14
// baseline (speedup 1.0000x reference)
#include <cuda_runtime.h>
#include <cuda_fp16.h>
#include <cstdint>

#define F_   512
#define KN_  16384       // k*n per (b,f)
#define FKN  8388608     // F_*KN_
#define STAGE 20480      // 20KB per stage: X 16KB + W 4KB

// -------- device scratch (allocs forbidden) --------
__device__ __half g_W[512 * 512];          // W fp16
__device__ __half g_xh[(size_t)8 * FKN];   // x fp16, original layout (128MB)

// -------- prep: W -> fp16 --------
__global__ void prep_w(const float* __restrict__ W) {
    int i = blockIdx.x * 512 + threadIdx.x;
    g_W[i] = __float2half(W[i]);
}

// -------- prep: x -> fp16, same layout --------
__global__ void __launch_bounds__(256) prep_xh(const float* __restrict__ x) {
    size_t i = (size_t)blockIdx.x * 256 + threadIdx.x;   // *4 elements
    float4 v = ((const float4*)x)[i];
    __half2 h0 = __floats2half2_rn(v.x, v.y);
    __half2 h1 = __floats2half2_rn(v.z, v.w);
    uint2 u;
    u.x = *(uint32_t*)&h0;
    u.y = *(uint32_t*)&h1;
    ((uint2*)g_xh)[i] = u;
}

// -------- PTX helpers (baseline PTX, plain sm_103 target OK) --------
static __device__ __forceinline__ uint32_t smem_u32(const void* p) {
    uint32_t a;
    asm("{ .reg .u64 t; cvta.to.shared.u64 t, %1; cvt.u32.u64 %0, t; }" : "=r"(a) : "l"(p));
    return a;
}
static __device__ __forceinline__ void cpa16(uint32_t dst, const void* src) {
    asm volatile("cp.async.cg.shared.global [%0], [%1], 16;"
                 :: "r"(dst), "l"(__cvta_generic_to_global(src)));
}
static __device__ __forceinline__ void cp_commit() {
    asm volatile("cp.async.commit_group;" ::: "memory");
}
template <int NN> static __device__ __forceinline__ void cp_wait() {
    asm volatile("cp.async.wait_group %0;" :: "n"(NN) : "memory");
}
static __device__ __forceinline__ void ldsm4(uint32_t* r, uint32_t a) {
    asm volatile("ldmatrix.sync.aligned.m8n8.x4.shared.b16 {%0,%1,%2,%3}, [%4];"
                 : "=r"(r[0]), "=r"(r[1]), "=r"(r[2]), "=r"(r[3]) : "r"(a));
}
static __device__ __forceinline__ void ldsm4t(uint32_t* r, uint32_t a) {
    asm volatile("ldmatrix.sync.aligned.m8n8.x4.trans.shared.b16 {%0,%1,%2,%3}, [%4];"
                 : "=r"(r[0]), "=r"(r[1]), "=r"(r[2]), "=r"(r[3]) : "r"(a));
}
static __device__ __forceinline__ void mma16816(float* c,
        uint32_t a0, uint32_t a1, uint32_t a2, uint32_t a3,
        uint32_t b0, uint32_t b1) {
    asm volatile(
        "mma.sync.aligned.m16n8k16.row.col.f32.f16.f16.f32 "
        "{%0,%1,%2,%3}, {%4,%5,%6,%7}, {%8,%9}, {%0,%1,%2,%3};"
        : "+f"(c[0]), "+f"(c[1]), "+f"(c[2]), "+f"(c[3])
        : "r"(a0), "r"(a1), "r"(a2), "r"(a3), "r"(b0), "r"(b1));
}

// ---------------- fused kernel ----------------
// CTA: 64 g x 256 tau (= 8k x 32n). 256 threads, 8 warps = 2 wm x 4 wn.
// 2 CTAs/SM. Pipeline: 3 stages of 20KB, lookahead 2, wait_group<1> (R12 config).
//   X sub fh at s*20480 + fh*8192          : 16 f-rows x 512B, chunk swz ^(f&7)
//   W sub fh at s*20480 + 16384 + fh*2048  : 64 g-rows x 32B, chunk swz (g>>2)&1
// Epilogue reuses region as ds[64][264] f32 (67584 B), single phase, vectorized.
__global__ void __launch_bounds__(256, 2)
lnkr_mma_kernel(const float* __restrict__ x, float* __restrict__ out) {
    extern __shared__ char sm_[];
    const uint32_t smb = smem_u32(sm_);

    const int t    = threadIdx.x;
    const int lane = t & 31;
    const int w    = t >> 5;
    const int wm   = w >> 2;         // 0..1: 32-g group
    const int wn   = w & 3;          // 0..3: 64-tau group
    const int lq   = lane >> 2;
    const int lc   = lane & 3;
    const int lr   = lane & 7;
    const int grp  = lane >> 3;
    const int gc    = blockIdx.x & 7;            // 0..7: 64-g chunk
    const int ntile = blockIdx.x >> 3;           // 0..63
    const int b     = blockIdx.y;
    const int nbase = ntile * 32;

    // ---- cp.async decode ----
    // X: 1024 granules/slab (32 f x 32 chunks); each thread does 4 (j = 0..3)
    const __half* xsrcj[4];
    uint32_t      xdstj[4];
#pragma unroll
    for (int j = 0; j < 4; ++j) {
        int id = t + j * 256;
        int fh = id >> 9;            // 16-f sub-block 0..1
        int r  = id & 511;
        int fr = r >> 5;             // f row in sub-block
        int c  = r & 31;             // 16B chunk (k = c>>2, npart = c&3)
        xsrcj[j] = g_xh + (size_t)b * FKN + (size_t)(fh * 16 + fr) * KN_
                        + (c >> 2) * 2048 + nbase + (c & 3) * 8;
        xdstj[j] = fh * 8192 + fr * 512 + ((c ^ (fr & 7)) << 4);
    }
    // W: 256 granules/slab (2 fh x 64 rows x 2 chunks); each thread does 1
    const int wfh   = t >> 7;              // f half
    const int wgr   = (t & 127) >> 1;      // g row 0..63
    const int wpart = t & 1;
    const __half* wsrc0 = g_W + (size_t)(gc * 64 + wgr) * 512 + wfh * 16 + wpart * 8;
    const uint32_t wdst = 16384 + wfh * 2048 + wgr * 32
                        + ((wpart ^ ((wgr >> 2) & 1)) << 4);

    // ---- ldmatrix offsets (sub-block-relative, identical to R8/R10/R12) ----
    uint32_t offB[4];
#pragma unroll
    for (int q = 0; q < 4; ++q) {
        int f  = (grp & 1) * 8 + lr;
        int tc = wn * 8 + 2 * q + (grp >> 1);
        offB[q] = f * 512 + ((tc ^ (f & 7)) << 4);
    }
    uint32_t offA[2];
#pragma unroll
    for (int mi = 0; mi < 2; ++mi) {
        int g  = wm * 32 + mi * 16 + (grp & 1) * 8 + lr;
        int ch = (grp >> 1) ^ ((g >> 2) & 1);
        offA[mi] = g * 32 + (ch << 4);
    }

    float acc[2][8][4];
#pragma unroll
    for (int mi = 0; mi < 2; ++mi)
#pragma unroll
        for (int ni = 0; ni < 8; ++ni)
#pragma unroll
            for (int q = 0; q < 4; ++q) acc[mi][ni][q] = 0.0f;

    // ---- stage loader: slab s covers f0 = s*32 ----
    auto load_slab = [&](int s) {
        uint32_t base = smb + (s % 3) * STAGE;
#pragma unroll
        for (int j = 0; j < 4; ++j)
            cpa16(base + xdstj[j], xsrcj[j] + (size_t)s * 32 * KN_);
        cpa16(base + wdst, wsrc0 + s * 32);
    };

    // ---- prologue: 2 stages in flight ----
    load_slab(0); cp_commit();
    load_slab(1); cp_commit();

    // ---- K loop: 16 slabs of 32 f ----
    for (int c = 0; c < 16; ++c) {
        cp_wait<1>();
        __syncthreads();
        if (c + 2 < 16) load_slab(c + 2);
        cp_commit();   // uniform -> wait_group<1> stays valid

        const uint32_t base = smb + (c % 3) * STAGE;
#pragma unroll
        for (int fh = 0; fh < 2; ++fh) {
            const uint32_t xb = base + fh * 8192;
            const uint32_t wb = base + 16384 + fh * 2048;

            uint32_t A[2][4], Bx[4][4];
            ldsm4(A[0], wb + offA[0]);
            ldsm4(A[1], wb + offA[1]);
#pragma unroll
            for (int q = 0; q < 4; ++q) ldsm4t(Bx[q], xb + offB[q]);

#pragma unroll
            for (int q = 0; q < 4; ++q) {
#pragma unroll
                for (int j = 0; j < 2; ++j) {
                    uint32_t b0 = Bx[q][2 * j], b1 = Bx[q][2 * j + 1];
                    int ni = 2 * q + j;
#pragma unroll
                    for (int mi = 0; mi < 2; ++mi)
                        mma16816(acc[mi][ni], A[mi][0], A[mi][1], A[mi][2], A[mi][3], b0, b1);
                }
            }
        }
    }
    __syncthreads();

    // ---- epilogue: acc -> smem ds (R12-identical), then vectorized consume ----
    float* ds = (float*)sm_;          // [64][264] f32
    const __half* xh = g_xh;
#pragma unroll
    for (int mi = 0; mi < 2; ++mi)
#pragma unroll
        for (int ni = 0; ni < 8; ++ni) {
            int row  = wm * 32 + mi * 16 + lq;
            int tcol = wn * 64 + ni * 8 + lc * 2;
            float* pp = ds + row * 264 + tcol;
            pp[0] = acc[mi][ni][0];
            pp[1] = acc[mi][ni][1];
            pp[8 * 264]     = acc[mi][ni][2];
            pp[8 * 264 + 1] = acc[mi][ni][3];
        }
    __syncthreads();

    // consume: thread -> (g_l = t>>2, 8 consecutive n at n0 = (t&3)*8)
    {
        const int g_l = t >> 2;
        const int n0  = (t & 3) * 8;
        const int g   = gc * 64 + g_l;
        const size_t gbase = (size_t)b * FKN + (size_t)g * KN_ + nbase + n0;
        const __half* xp = xh + gbase;
        float* op = out + gbase;
        const float* dsp = ds + g_l * 264 + n0;

        // load x (fp16) for all 8 k (vector LDG.128), convert to float
        float XF[8][8];
#pragma unroll
        for (int k = 0; k < 8; ++k) {
            uint4 xv = *(const uint4*)(xp + (size_t)k * 2048);
            const __half2* hp = (const __half2*)&xv;
#pragma unroll
            for (int p = 0; p < 4; ++p) {
                float2 f = __half22float2(hp[p]);
                XF[k][2 * p]     = f.x;
                XF[k][2 * p + 1] = f.y;
            }
        }

        // kf[j] = sum_b coef_b(x[j]) * d_b[j]
        // b=0:(12x0-6x4)  b=1:6x3  b=2:6x6  b=3:6x1
        // b=4:(12x4-6x0)  b=5:6x7  b=6:6x2  b=7:6x5
        float kf[8];
#pragma unroll
        for (int j = 0; j < 8; ++j) kf[j] = 0.0f;
#pragma unroll
        for (int k = 0; k < 8; ++k) {
            float4 dA = *(const float4*)(dsp + k * 32);
            float4 dB = *(const float4*)(dsp + k * 32 + 4);
            float dv[8] = {dA.x, dA.y, dA.z, dA.w, dB.x, dB.y, dB.z, dB.w};
#pragma unroll
            for (int j = 0; j < 8; ++j) {
                float cxx;
                if      (k == 0) cxx = 12.0f * XF[0][j] - 6.0f * XF[4][j];
                else if (k == 1) cxx = 6.0f * XF[3][j];
                else if (k == 2) cxx = 6.0f * XF[6][j];
                else if (k == 3) cxx = 6.0f * XF[1][j];
                else if (k == 4) cxx = 12.0f * XF[4][j] - 6.0f * XF[0][j];
                else if (k == 5) cxx = 6.0f * XF[7][j];
                else if (k == 6) cxx = 6.0f * XF[2][j];
                else             cxx = 6.0f * XF[5][j];
                kf[j] = fmaf(cxx, dv[j], kf[j]);
            }
        }

        // gated output, vector stores
#pragma unroll
        for (int k = 0; k < 8; ++k) {
            float4 dA = *(const float4*)(dsp + k * 32);
            float4 dB = *(const float4*)(dsp + k * 32 + 4);
            float dv[8] = {dA.x, dA.y, dA.z, dA.w, dB.x, dB.y, dB.z, dB.w};
            float ov[8];
#pragma unroll
            for (int j = 0; j < 8; ++j)
                ov[j] = (kf[j] > 0.0f) ? fmaf(kf[j], dv[j], XF[k][j]) : XF[k][j];
            *(float4*)(op + (size_t)k * 2048)     = make_float4(ov[0], ov[1], ov[2], ov[3]);
            *(float4*)(op + (size_t)k * 2048 + 4) = make_float4(ov[4], ov[5], ov[6], ov[7]);
        }
    }
}

extern "C" void kernel_launch(void* const* d_in, const int* in_sizes, int n_in,
                              void* d_out, int out_size)
{
    const float* a0 = (const float*)d_in[0];
    const float* a1 = (const float*)d_in[1];
    const float* x = a0; const float* W = a1;
    if (n_in >= 2 && in_sizes[0] < in_sizes[1]) { x = a1; W = a0; }

    cudaFuncSetAttribute(lnkr_mma_kernel,
                         cudaFuncAttributeMaxDynamicSharedMemorySize, 67584);

    prep_w<<<512, 512>>>(W);
    prep_xh<<<65536, 256>>>(x);
    lnkr_mma_kernel<<<dim3(512, 8), 256, 67584>>>(x, (float*)d_out);
}

// round 15
// speedup vs baseline: 1.1252x; 1.1252x over previous
#include <cuda_runtime.h>
#include <cuda_fp16.h>
#include <cstdint>

#define F_   512
#define KN_  16384       // k*n per (b,f)
#define FKN  8388608     // F_*KN_
#define STAGE 20480      // 20KB per stage: X 16KB + W 4KB

// -------- device scratch (allocs forbidden) --------
__device__ __half g_W[512 * 512];          // W fp16
__device__ __half g_xh[(size_t)8 * FKN];   // x fp16, original layout (128MB)

// -------- prep: W -> fp16 --------
__global__ void prep_w(const float* __restrict__ W) {
    int i = blockIdx.x * 512 + threadIdx.x;
    g_W[i] = __float2half(W[i]);
}

// -------- prep: x -> fp16, same layout --------
__global__ void __launch_bounds__(256) prep_xh(const float* __restrict__ x) {
    size_t i = (size_t)blockIdx.x * 256 + threadIdx.x;   // *4 elements
    float4 v = ((const float4*)x)[i];
    __half2 h0 = __floats2half2_rn(v.x, v.y);
    __half2 h1 = __floats2half2_rn(v.z, v.w);
    uint2 u;
    u.x = *(uint32_t*)&h0;
    u.y = *(uint32_t*)&h1;
    ((uint2*)g_xh)[i] = u;
}

// -------- PTX helpers (baseline PTX, plain sm_103 target OK) --------
static __device__ __forceinline__ uint32_t smem_u32(const void* p) {
    uint32_t a;
    asm("{ .reg .u64 t; cvta.to.shared.u64 t, %1; cvt.u32.u64 %0, t; }" : "=r"(a) : "l"(p));
    return a;
}
static __device__ __forceinline__ void cpa16(uint32_t dst, const void* src) {
    asm volatile("cp.async.cg.shared.global [%0], [%1], 16;"
                 :: "r"(dst), "l"(__cvta_generic_to_global(src)));
}
static __device__ __forceinline__ void cp_commit() {
    asm volatile("cp.async.commit_group;" ::: "memory");
}
template <int NN> static __device__ __forceinline__ void cp_wait() {
    asm volatile("cp.async.wait_group %0;" :: "n"(NN) : "memory");
}
static __device__ __forceinline__ void ldsm4(uint32_t* r, uint32_t a) {
    asm volatile("ldmatrix.sync.aligned.m8n8.x4.shared.b16 {%0,%1,%2,%3}, [%4];"
                 : "=r"(r[0]), "=r"(r[1]), "=r"(r[2]), "=r"(r[3]) : "r"(a));
}
static __device__ __forceinline__ void ldsm4t(uint32_t* r, uint32_t a) {
    asm volatile("ldmatrix.sync.aligned.m8n8.x4.trans.shared.b16 {%0,%1,%2,%3}, [%4];"
                 : "=r"(r[0]), "=r"(r[1]), "=r"(r[2]), "=r"(r[3]) : "r"(a));
}
static __device__ __forceinline__ void mma16816(float* c,
        uint32_t a0, uint32_t a1, uint32_t a2, uint32_t a3,
        uint32_t b0, uint32_t b1) {
    asm volatile(
        "mma.sync.aligned.m16n8k16.row.col.f32.f16.f16.f32 "
        "{%0,%1,%2,%3}, {%4,%5,%6,%7}, {%8,%9}, {%0,%1,%2,%3};"
        : "+f"(c[0]), "+f"(c[1]), "+f"(c[2]), "+f"(c[3])
        : "r"(a0), "r"(a1), "r"(a2), "r"(a3), "r"(b0), "r"(b1));
}

// ---------------- fused kernel ----------------
// CTA: 64 g x 256 tau (= 8k x 32n). 256 threads, 8 warps = 2 wm x 4 wn.
// 2 CTAs/SM. Pipeline: 3 stages of 20KB, lookahead 2, wait_group<1> (R12 config).
//   X sub fh at s*20480 + fh*8192          : 16 f-rows x 512B, chunk swz ^(f&7)
//   W sub fh at s*20480 + 16384 + fh*2048  : 64 g-rows x 32B, chunk swz (g>>2)&1
// Epilogue reuses region as ds[64][264] f32 (67584 B); consume is n-pairwise.
__global__ void __launch_bounds__(256, 2)
lnkr_mma_kernel(const float* __restrict__ x, float* __restrict__ out) {
    extern __shared__ char sm_[];
    const uint32_t smb = smem_u32(sm_);

    const int t    = threadIdx.x;
    const int lane = t & 31;
    const int w    = t >> 5;
    const int wm   = w >> 2;         // 0..1: 32-g group
    const int wn   = w & 3;          // 0..3: 64-tau group
    const int lq   = lane >> 2;
    const int lc   = lane & 3;
    const int lr   = lane & 7;
    const int grp  = lane >> 3;
    const int gc    = blockIdx.x & 7;            // 0..7: 64-g chunk
    const int ntile = blockIdx.x >> 3;           // 0..63
    const int b     = blockIdx.y;
    const int nbase = ntile * 32;

    // ---- cp.async decode ----
    // X: 1024 granules/slab (32 f x 32 chunks); each thread does 4 (j = 0..3)
    const __half* xsrcj[4];
    uint32_t      xdstj[4];
#pragma unroll
    for (int j = 0; j < 4; ++j) {
        int id = t + j * 256;
        int fh = id >> 9;            // 16-f sub-block 0..1
        int r  = id & 511;
        int fr = r >> 5;             // f row in sub-block
        int c  = r & 31;             // 16B chunk (k = c>>2, npart = c&3)
        xsrcj[j] = g_xh + (size_t)b * FKN + (size_t)(fh * 16 + fr) * KN_
                        + (c >> 2) * 2048 + nbase + (c & 3) * 8;
        xdstj[j] = fh * 8192 + fr * 512 + ((c ^ (fr & 7)) << 4);
    }
    // W: 256 granules/slab (2 fh x 64 rows x 2 chunks); each thread does 1
    const int wfh   = t >> 7;              // f half
    const int wgr   = (t & 127) >> 1;      // g row 0..63
    const int wpart = t & 1;
    const __half* wsrc0 = g_W + (size_t)(gc * 64 + wgr) * 512 + wfh * 16 + wpart * 8;
    const uint32_t wdst = 16384 + wfh * 2048 + wgr * 32
                        + ((wpart ^ ((wgr >> 2) & 1)) << 4);

    // ---- ldmatrix offsets (sub-block-relative, identical to R8/R10/R12) ----
    uint32_t offB[4];
#pragma unroll
    for (int q = 0; q < 4; ++q) {
        int f  = (grp & 1) * 8 + lr;
        int tc = wn * 8 + 2 * q + (grp >> 1);
        offB[q] = f * 512 + ((tc ^ (f & 7)) << 4);
    }
    uint32_t offA[2];
#pragma unroll
    for (int mi = 0; mi < 2; ++mi) {
        int g  = wm * 32 + mi * 16 + (grp & 1) * 8 + lr;
        int ch = (grp >> 1) ^ ((g >> 2) & 1);
        offA[mi] = g * 32 + (ch << 4);
    }

    float acc[2][8][4];
#pragma unroll
    for (int mi = 0; mi < 2; ++mi)
#pragma unroll
        for (int ni = 0; ni < 8; ++ni)
#pragma unroll
            for (int q = 0; q < 4; ++q) acc[mi][ni][q] = 0.0f;

    // ---- stage loader: slab s covers f0 = s*32 ----
    auto load_slab = [&](int s) {
        uint32_t base = smb + (s % 3) * STAGE;
#pragma unroll
        for (int j = 0; j < 4; ++j)
            cpa16(base + xdstj[j], xsrcj[j] + (size_t)s * 32 * KN_);
        cpa16(base + wdst, wsrc0 + s * 32);
    };

    // ---- prologue: 2 stages in flight ----
    load_slab(0); cp_commit();
    load_slab(1); cp_commit();

    // ---- K loop: 16 slabs of 32 f ----
    for (int c = 0; c < 16; ++c) {
        cp_wait<1>();
        __syncthreads();
        if (c + 2 < 16) load_slab(c + 2);
        cp_commit();   // uniform -> wait_group<1> stays valid

        const uint32_t base = smb + (c % 3) * STAGE;
#pragma unroll
        for (int fh = 0; fh < 2; ++fh) {
            const uint32_t xb = base + fh * 8192;
            const uint32_t wb = base + 16384 + fh * 2048;

            uint32_t A[2][4], Bx[4][4];
            ldsm4(A[0], wb + offA[0]);
            ldsm4(A[1], wb + offA[1]);
#pragma unroll
            for (int q = 0; q < 4; ++q) ldsm4t(Bx[q], xb + offB[q]);

#pragma unroll
            for (int q = 0; q < 4; ++q) {
#pragma unroll
                for (int j = 0; j < 2; ++j) {
                    uint32_t b0 = Bx[q][2 * j], b1 = Bx[q][2 * j + 1];
                    int ni = 2 * q + j;
#pragma unroll
                    for (int mi = 0; mi < 2; ++mi)
                        mma16816(acc[mi][ni], A[mi][0], A[mi][1], A[mi][2], A[mi][3], b0, b1);
                }
            }
        }
    }
    __syncthreads();

    // ---- epilogue: acc -> smem ds (R12-identical) ----
    float* ds = (float*)sm_;          // [64][264] f32
    const __half* xh = g_xh;
#pragma unroll
    for (int mi = 0; mi < 2; ++mi)
#pragma unroll
        for (int ni = 0; ni < 8; ++ni) {
            int row  = wm * 32 + mi * 16 + lq;
            int tcol = wn * 64 + ni * 8 + lc * 2;
            float* pp = ds + row * 264 + tcol;
            pp[0] = acc[mi][ni][0];
            pp[1] = acc[mi][ni][1];
            pp[8 * 264]     = acc[mi][ni][2];
            pp[8 * 264 + 1] = acc[mi][ni][3];
        }
    __syncthreads();

    // ---- consume: 64 g x 16 n-pairs = 1024 items; 256 threads x 4 ----
#pragma unroll
    for (int it = 0; it < 4; ++it) {
        int id  = t + it * 256;
        int g_l = id >> 4;               // 0..63
        int np  = id & 15;               // n-pair index
        int g   = gc * 64 + g_l;
        size_t base = (size_t)b * FKN + (size_t)g * KN_ + nbase + np * 2;

        float2 xs[8], dd[8];
#pragma unroll
        for (int k = 0; k < 8; ++k) {
            __half2 hx = *(const __half2*)(xh + base + (size_t)k * 2048);
            xs[k] = __half22float2(hx);
            dd[k] = *(const float2*)(ds + g_l * 264 + k * 32 + np * 2);
        }
        // Killing Gram nonzeros: G00=G44=12, G04=G40=-6, G13=G31=G26=G62=G57=G75=6
        float kf0 = 6.0f * (2.0f * xs[0].x * dd[0].x + 2.0f * xs[4].x * dd[4].x
                            - xs[0].x * dd[4].x - xs[4].x * dd[0].x
                            + xs[1].x * dd[3].x + xs[3].x * dd[1].x
                            + xs[2].x * dd[6].x + xs[6].x * dd[2].x
                            + xs[5].x * dd[7].x + xs[7].x * dd[5].x);
        float kf1 = 6.0f * (2.0f * xs[0].y * dd[0].y + 2.0f * xs[4].y * dd[4].y
                            - xs[0].y * dd[4].y - xs[4].y * dd[0].y
                            + xs[1].y * dd[3].y + xs[3].y * dd[1].y
                            + xs[2].y * dd[6].y + xs[6].y * dd[2].y
                            + xs[5].y * dd[7].y + xs[7].y * dd[5].y);
        bool p0 = (kf0 > 0.0f), p1 = (kf1 > 0.0f);
#pragma unroll
        for (int k = 0; k < 8; ++k) {
            float2 ov;
            ov.x = p0 ? fmaf(kf0, dd[k].x, xs[k].x) : xs[k].x;
            ov.y = p1 ? fmaf(kf1, dd[k].y, xs[k].y) : xs[k].y;
            *(float2*)(out + base + (size_t)k * 2048) = ov;
        }
    }
}

extern "C" void kernel_launch(void* const* d_in, const int* in_sizes, int n_in,
                              void* d_out, int out_size)
{
    const float* a0 = (const float*)d_in[0];
    const float* a1 = (const float*)d_in[1];
    const float* x = a0; const float* W = a1;
    if (n_in >= 2 && in_sizes[0] < in_sizes[1]) { x = a1; W = a0; }

    cudaFuncSetAttribute(lnkr_mma_kernel,
                         cudaFuncAttributeMaxDynamicSharedMemorySize, 67584);

    prep_w<<<512, 512>>>(W);
    prep_xh<<<65536, 256>>>(x);
    lnkr_mma_kernel<<<dim3(512, 8), 256, 67584>>>(x, (float*)d_out);
}